// round 1
// baseline (speedup 1.0000x reference)
#include <cuda_runtime.h>
#include <cstddef>

// Problem constants (fixed by the reference setup_inputs)
#define NQ 16384
#define NV 8192
#define QPB 4           // query rows per CTA
#define THREADS 512
#define SMEM_W_BYTES (QPB * NV * 4)   // 131072 bytes

// Packed voxel data (scratch via __device__ globals; allocation-free)
__device__ float4 g_vox_a[NV];   // (-2*cx, -2*cy, -2*cz, cx^2+cy^2+cz^2)
__device__ float4 g_vox_f[NV];   // features
__device__ float  g_vox_s[NV];   // sizes

__device__ __forceinline__ float fast_sqrt(float x) {
    float r; asm("sqrt.approx.f32 %0, %1;" : "=f"(r) : "f"(x)); return r;
}
__device__ __forceinline__ float fast_ex2(float x) {
    float r; asm("ex2.approx.f32 %0, %1;" : "=f"(r) : "f"(x)); return r;
}
__device__ __forceinline__ float warp_sum(float v) {
    #pragma unroll
    for (int o = 16; o; o >>= 1) v += __shfl_xor_sync(0xffffffffu, v, o);
    return v;
}

__global__ void pack_voxels_kernel(const float* __restrict__ vc,
                                   const float* __restrict__ vf,
                                   const float* __restrict__ vs) {
    int v = blockIdx.x * blockDim.x + threadIdx.x;
    if (v < NV) {
        float x = vc[3 * v + 0], y = vc[3 * v + 1], z = vc[3 * v + 2];
        g_vox_a[v] = make_float4(-2.f * x, -2.f * y, -2.f * z,
                                 x * x + y * y + z * z);
        g_vox_f[v] = make_float4(vf[4 * v + 0], vf[4 * v + 1],
                                 vf[4 * v + 2], vf[4 * v + 3]);
        g_vox_s[v] = vs[v];
    }
}

__global__ __launch_bounds__(THREADS, 1)
void svg_main_kernel(const float* __restrict__ qp, float* __restrict__ out) {
    extern __shared__ float s_w[];          // [QPB][NV] unnormalized weights
    __shared__ float s_red[QPB * 6];        // per q: sum, f0..f3, size
    __shared__ float s_inv[QPB];

    const int tid   = threadIdx.x;
    const int lane  = tid & 31;
    const int qbase = blockIdx.x * QPB;

    if (tid < QPB * 6) s_red[tid] = 0.f;

    // Load the QPB query points (broadcast loads, L1-friendly)
    float qx[QPB], qy[QPB], qz[QPB], q2[QPB];
    #pragma unroll
    for (int q = 0; q < QPB; q++) {
        const float* p = qp + (size_t)(qbase + q) * 3;
        float x = __ldg(p + 0), y = __ldg(p + 1), z = __ldg(p + 2);
        qx[q] = x; qy[q] = y; qz[q] = z;
        q2[q] = x * x + y * y + z * z;
    }

    float sum[QPB], a0[QPB], a1[QPB], a2[QPB], a3[QPB], as[QPB];
    #pragma unroll
    for (int q = 0; q < QPB; q++) {
        sum[q] = 0.f; a0[q] = 0.f; a1[q] = 0.f;
        a2[q] = 0.f; a3[q] = 0.f; as[q] = 0.f;
    }

    __syncthreads();   // s_red zero visible before post-loop atomics

    const float C = -0.72134752044f;  // -0.5 * log2(e)

    #pragma unroll 4
    for (int v = tid; v < NV; v += THREADS) {
        float4 A = g_vox_a[v];
        float4 F = g_vox_f[v];
        float  S = g_vox_s[v];
        #pragma unroll
        for (int q = 0; q < QPB; q++) {
            float d2 = q2[q] + A.w;
            d2 = fmaf(qx[q], A.x, d2);
            d2 = fmaf(qy[q], A.y, d2);
            d2 = fmaf(qz[q], A.z, d2);
            d2 = fmaxf(d2, 0.f);
            float d = fast_sqrt(d2);
            float w = fast_ex2(d * C);           // exp(-d/2)
            sum[q] += w;
            a0[q] = fmaf(w, F.x, a0[q]);
            a1[q] = fmaf(w, F.y, a1[q]);
            a2[q] = fmaf(w, F.z, a2[q]);
            a3[q] = fmaf(w, F.w, a3[q]);
            as[q] = fmaf(w, S,   as[q]);
            s_w[q * NV + v] = w;
        }
    }

    // Block reduction: warp shuffle, then one smem atomic per warp per value
    #pragma unroll
    for (int q = 0; q < QPB; q++) {
        float r0 = warp_sum(sum[q]);
        float r1 = warp_sum(a0[q]);
        float r2 = warp_sum(a1[q]);
        float r3 = warp_sum(a2[q]);
        float r4 = warp_sum(a3[q]);
        float r5 = warp_sum(as[q]);
        if (lane == 0) {
            atomicAdd(&s_red[q * 6 + 0], r0);
            atomicAdd(&s_red[q * 6 + 1], r1);
            atomicAdd(&s_red[q * 6 + 2], r2);
            atomicAdd(&s_red[q * 6 + 3], r3);
            atomicAdd(&s_red[q * 6 + 4], r4);
            atomicAdd(&s_red[q * 6 + 5], r5);
        }
    }
    __syncthreads();

    // Epilogue: densities / colors / sizes (+ publish inv for weight scaling)
    if (tid < QPB) {
        int q = tid;
        float inv = 1.f / (s_red[q * 6 + 0] + 1e-8f);
        s_inv[q] = inv;
        float f0 = s_red[q * 6 + 1] * inv;
        float f1 = s_red[q * 6 + 2] * inv;
        float f2 = s_red[q * 6 + 3] * inv;
        float f3 = s_red[q * 6 + 4] * inv;
        float sz = s_red[q * 6 + 5] * inv;
        int row = qbase + q;
        // softplus (stable)
        out[row] = fmaxf(f0, 0.f) + log1pf(__expf(-fabsf(f0)));
        // sigmoid colors
        float* oc = out + NQ + (size_t)row * 3;
        oc[0] = 1.f / (1.f + __expf(-f1));
        oc[1] = 1.f / (1.f + __expf(-f2));
        oc[2] = 1.f / (1.f + __expf(-f3));
        out[4 * NQ + row] = sz;
    }
    __syncthreads();

    // Normalize + store weight rows (vectorized, coalesced)
    float4* ow = (float4*)(out + (size_t)5 * NQ + (size_t)qbase * NV);
    #pragma unroll
    for (int q = 0; q < QPB; q++) {
        float inv = s_inv[q];
        const float4* sw = (const float4*)(s_w + q * NV);
        #pragma unroll
        for (int i = tid; i < NV / 4; i += THREADS) {
            float4 w4 = sw[i];
            w4.x *= inv; w4.y *= inv; w4.z *= inv; w4.w *= inv;
            ow[(size_t)q * (NV / 4) + i] = w4;
        }
    }
}

extern "C" void kernel_launch(void* const* d_in, const int* in_sizes, int n_in,
                              void* d_out, int out_size) {
    const float* qp = (const float*)d_in[0];  // query_points [NQ,3]
    const float* vc = (const float*)d_in[1];  // voxel_coords [NV,3]
    const float* vf = (const float*)d_in[2];  // voxel_features [NV,4]
    const float* vs = (const float*)d_in[3];  // voxel_sizes [NV]
    float* out = (float*)d_out;

    pack_voxels_kernel<<<(NV + 255) / 256, 256>>>(vc, vf, vs);

    cudaFuncSetAttribute(svg_main_kernel,
                         cudaFuncAttributeMaxDynamicSharedMemorySize,
                         SMEM_W_BYTES);
    svg_main_kernel<<<NQ / QPB, THREADS, SMEM_W_BYTES>>>(qp, out);
}

// round 2
// speedup vs baseline: 1.2793x; 1.2793x over previous
#include <cuda_runtime.h>
#include <cstddef>

// Problem constants (fixed by the reference setup_inputs)
#define NQ 16384
#define NV 8192
#define QPB 2           // query rows per CTA
#define THREADS 256
#define SMEM_W_BYTES (QPB * NV * 4)   // 65536 bytes

// Packed voxel data (scratch via __device__ globals; allocation-free)
__device__ float4 g_vox_a[NV];   // (-2*cx, -2*cy, -2*cz, cx^2+cy^2+cz^2)
__device__ float4 g_vox_f[NV];   // features
__device__ float  g_vox_s[NV];   // sizes

__device__ __forceinline__ float fast_sqrt(float x) {
    float r; asm("sqrt.approx.f32 %0, %1;" : "=f"(r) : "f"(x)); return r;
}
__device__ __forceinline__ float fast_ex2(float x) {
    float r; asm("ex2.approx.f32 %0, %1;" : "=f"(r) : "f"(x)); return r;
}
__device__ __forceinline__ float warp_sum(float v) {
    #pragma unroll
    for (int o = 16; o; o >>= 1) v += __shfl_xor_sync(0xffffffffu, v, o);
    return v;
}
__device__ __forceinline__ void st_stream_f4(float4* p, float4 v) {
    asm volatile("st.global.cs.v4.f32 [%0], {%1,%2,%3,%4};"
                 :: "l"(p), "f"(v.x), "f"(v.y), "f"(v.z), "f"(v.w) : "memory");
}

__global__ void pack_voxels_kernel(const float* __restrict__ vc,
                                   const float* __restrict__ vf,
                                   const float* __restrict__ vs) {
    int v = blockIdx.x * blockDim.x + threadIdx.x;
    if (v < NV) {
        float x = vc[3 * v + 0], y = vc[3 * v + 1], z = vc[3 * v + 2];
        g_vox_a[v] = make_float4(-2.f * x, -2.f * y, -2.f * z,
                                 x * x + y * y + z * z);
        g_vox_f[v] = make_float4(vf[4 * v + 0], vf[4 * v + 1],
                                 vf[4 * v + 2], vf[4 * v + 3]);
        g_vox_s[v] = vs[v];
    }
}

__global__ __launch_bounds__(THREADS, 3)
void svg_main_kernel(const float* __restrict__ qp, float* __restrict__ out) {
    extern __shared__ float s_w[];          // [QPB][NV] unnormalized weights
    __shared__ float s_red[QPB * 6];        // per q: sum, f0..f3, size
    __shared__ float s_inv[QPB];

    const int tid   = threadIdx.x;
    const int lane  = tid & 31;
    const int qbase = blockIdx.x * QPB;

    if (tid < QPB * 6) s_red[tid] = 0.f;

    // Load the QPB query points (broadcast loads, L1-friendly)
    float qx[QPB], qy[QPB], qz[QPB], q2[QPB];
    #pragma unroll
    for (int q = 0; q < QPB; q++) {
        const float* p = qp + (size_t)(qbase + q) * 3;
        float x = __ldg(p + 0), y = __ldg(p + 1), z = __ldg(p + 2);
        qx[q] = x; qy[q] = y; qz[q] = z;
        q2[q] = x * x + y * y + z * z;
    }

    float sum[QPB], a0[QPB], a1[QPB], a2[QPB], a3[QPB], as[QPB];
    #pragma unroll
    for (int q = 0; q < QPB; q++) {
        sum[q] = 0.f; a0[q] = 0.f; a1[q] = 0.f;
        a2[q] = 0.f; a3[q] = 0.f; as[q] = 0.f;
    }

    __syncthreads();   // s_red zero visible before post-loop atomics

    const float C = -0.72134752044f;  // -0.5 * log2(e)

    #pragma unroll 4
    for (int v = tid; v < NV; v += THREADS) {
        float4 A = g_vox_a[v];
        float4 F = g_vox_f[v];
        float  S = g_vox_s[v];
        #pragma unroll
        for (int q = 0; q < QPB; q++) {
            float d2 = q2[q] + A.w;
            d2 = fmaf(qx[q], A.x, d2);
            d2 = fmaf(qy[q], A.y, d2);
            d2 = fmaf(qz[q], A.z, d2);
            d2 = fmaxf(d2, 0.f);
            float d = fast_sqrt(d2);
            float w = fast_ex2(d * C);           // exp(-d/2)
            sum[q] += w;
            a0[q] = fmaf(w, F.x, a0[q]);
            a1[q] = fmaf(w, F.y, a1[q]);
            a2[q] = fmaf(w, F.z, a2[q]);
            a3[q] = fmaf(w, F.w, a3[q]);
            as[q] = fmaf(w, S,   as[q]);
            s_w[q * NV + v] = w;
        }
    }

    // Block reduction: warp shuffle, then one smem atomic per warp per value
    #pragma unroll
    for (int q = 0; q < QPB; q++) {
        float r0 = warp_sum(sum[q]);
        float r1 = warp_sum(a0[q]);
        float r2 = warp_sum(a1[q]);
        float r3 = warp_sum(a2[q]);
        float r4 = warp_sum(a3[q]);
        float r5 = warp_sum(as[q]);
        if (lane == 0) {
            atomicAdd(&s_red[q * 6 + 0], r0);
            atomicAdd(&s_red[q * 6 + 1], r1);
            atomicAdd(&s_red[q * 6 + 2], r2);
            atomicAdd(&s_red[q * 6 + 3], r3);
            atomicAdd(&s_red[q * 6 + 4], r4);
            atomicAdd(&s_red[q * 6 + 5], r5);
        }
    }
    __syncthreads();

    // Epilogue: densities / colors / sizes (+ publish inv for weight scaling)
    if (tid < QPB) {
        int q = tid;
        float inv = 1.f / (s_red[q * 6 + 0] + 1e-8f);
        s_inv[q] = inv;
        float f0 = s_red[q * 6 + 1] * inv;
        float f1 = s_red[q * 6 + 2] * inv;
        float f2 = s_red[q * 6 + 3] * inv;
        float f3 = s_red[q * 6 + 4] * inv;
        float sz = s_red[q * 6 + 5] * inv;
        int row = qbase + q;
        // softplus (stable)
        out[row] = fmaxf(f0, 0.f) + log1pf(__expf(-fabsf(f0)));
        // sigmoid colors
        float* oc = out + NQ + (size_t)row * 3;
        oc[0] = 1.f / (1.f + __expf(-f1));
        oc[1] = 1.f / (1.f + __expf(-f2));
        oc[2] = 1.f / (1.f + __expf(-f3));
        out[4 * NQ + row] = sz;
    }
    __syncthreads();

    // Normalize + store weight rows (vectorized, coalesced, streaming)
    float4* ow = (float4*)(out + (size_t)5 * NQ + (size_t)qbase * NV);
    #pragma unroll
    for (int q = 0; q < QPB; q++) {
        float inv = s_inv[q];
        const float4* sw = (const float4*)(s_w + q * NV);
        #pragma unroll
        for (int i = tid; i < NV / 4; i += THREADS) {
            float4 w4 = sw[i];
            w4.x *= inv; w4.y *= inv; w4.z *= inv; w4.w *= inv;
            st_stream_f4(&ow[(size_t)q * (NV / 4) + i], w4);
        }
    }
}

extern "C" void kernel_launch(void* const* d_in, const int* in_sizes, int n_in,
                              void* d_out, int out_size) {
    const float* qp = (const float*)d_in[0];  // query_points [NQ,3]
    const float* vc = (const float*)d_in[1];  // voxel_coords [NV,3]
    const float* vf = (const float*)d_in[2];  // voxel_features [NV,4]
    const float* vs = (const float*)d_in[3];  // voxel_sizes [NV]
    float* out = (float*)d_out;

    pack_voxels_kernel<<<(NV + 255) / 256, 256>>>(vc, vf, vs);

    cudaFuncSetAttribute(svg_main_kernel,
                         cudaFuncAttributeMaxDynamicSharedMemorySize,
                         SMEM_W_BYTES);
    svg_main_kernel<<<NQ / QPB, THREADS, SMEM_W_BYTES>>>(qp, out);
}

// round 3
// speedup vs baseline: 1.2911x; 1.0092x over previous
#include <cuda_runtime.h>
#include <cstddef>

// Problem constants (fixed by the reference setup_inputs)
#define NQ 16384
#define NV 8192
#define QPB 8            // query rows per CTA (register-resident)
#define THREADS 256
#define VCACHE 3328      // voxels whose weights are cached in smem (13*256)
#define SMEM_WC_BYTES (QPB * VCACHE * 4)   // 106496 bytes

// Packed voxel data (scratch via __device__ globals; allocation-free)
__device__ float4 g_vox_a[NV];   // (-2*cx, -2*cy, -2*cz, cx^2+cy^2+cz^2)
__device__ float4 g_vox_f[NV];   // features
__device__ float  g_vox_s[NV];   // sizes

__device__ __forceinline__ float fast_sqrt(float x) {
    float r; asm("sqrt.approx.f32 %0, %1;" : "=f"(r) : "f"(x)); return r;
}
__device__ __forceinline__ float fast_ex2(float x) {
    float r; asm("ex2.approx.f32 %0, %1;" : "=f"(r) : "f"(x)); return r;
}
__device__ __forceinline__ float warp_sum(float v) {
    #pragma unroll
    for (int o = 16; o; o >>= 1) v += __shfl_xor_sync(0xffffffffu, v, o);
    return v;
}
__device__ __forceinline__ void st_stream_f(float* p, float v) {
    asm volatile("st.global.cs.f32 [%0], %1;" :: "l"(p), "f"(v) : "memory");
}

__global__ void pack_voxels_kernel(const float* __restrict__ vc,
                                   const float* __restrict__ vf,
                                   const float* __restrict__ vs) {
    int v = blockIdx.x * blockDim.x + threadIdx.x;
    if (v < NV) {
        float x = vc[3 * v + 0], y = vc[3 * v + 1], z = vc[3 * v + 2];
        g_vox_a[v] = make_float4(-2.f * x, -2.f * y, -2.f * z,
                                 x * x + y * y + z * z);
        g_vox_f[v] = make_float4(vf[4 * v + 0], vf[4 * v + 1],
                                 vf[4 * v + 2], vf[4 * v + 3]);
        g_vox_s[v] = vs[v];
    }
}

__global__ __launch_bounds__(THREADS, 2)
void svg_main_kernel(const float* __restrict__ qp, float* __restrict__ out) {
    extern __shared__ float s_wc[];        // [QPB][VCACHE] unnormalized w
    __shared__ float s_red[QPB * 6];       // per q: sum, f0..f3, size
    __shared__ float s_inv[QPB];           // 1/(sum+eps)
    __shared__ float s_L[QPB];             // log2(inv)

    const int tid   = threadIdx.x;
    const int lane  = tid & 31;
    const int qbase = blockIdx.x * QPB;

    if (tid < QPB * 6) s_red[tid] = 0.f;

    float qx[QPB], qy[QPB], qz[QPB], q2[QPB];
    #pragma unroll
    for (int q = 0; q < QPB; q++) {
        const float* p = qp + (size_t)(qbase + q) * 3;
        float x = __ldg(p + 0), y = __ldg(p + 1), z = __ldg(p + 2);
        qx[q] = x; qy[q] = y; qz[q] = z;
        q2[q] = x * x + y * y + z * z;
    }

    float sum[QPB], a0[QPB], a1[QPB], a2[QPB], a3[QPB], as[QPB];
    #pragma unroll
    for (int q = 0; q < QPB; q++) {
        sum[q] = 0.f; a0[q] = 0.f; a1[q] = 0.f;
        a2[q] = 0.f; a3[q] = 0.f; as[q] = 0.f;
    }

    __syncthreads();   // s_red zero visible

    const float C = -0.72134752044f;  // -0.5 * log2(e)

    // ---- Phase 1: accumulate sums; cache w for v < VCACHE ----
    #pragma unroll 2
    for (int v = tid; v < NV; v += THREADS) {
        float4 A = g_vox_a[v];
        float4 F = g_vox_f[v];
        float  S = g_vox_s[v];
        float w[QPB];
        #pragma unroll
        for (int q = 0; q < QPB; q++) {
            float d2 = q2[q] + A.w;
            d2 = fmaf(qx[q], A.x, d2);
            d2 = fmaf(qy[q], A.y, d2);
            d2 = fmaf(qz[q], A.z, d2);
            d2 = fmaxf(d2, 0.f);
            float d = fast_sqrt(d2);
            w[q] = fast_ex2(d * C);           // exp(-d/2)
            sum[q] += w[q];
            a0[q] = fmaf(w[q], F.x, a0[q]);
            a1[q] = fmaf(w[q], F.y, a1[q]);
            a2[q] = fmaf(w[q], F.z, a2[q]);
            a3[q] = fmaf(w[q], F.w, a3[q]);
            as[q] = fmaf(w[q], S,   as[q]);
        }
        if (v < VCACHE) {
            #pragma unroll
            for (int q = 0; q < QPB; q++) s_wc[q * VCACHE + v] = w[q];
        }
    }

    // ---- Block reduction ----
    #pragma unroll
    for (int q = 0; q < QPB; q++) {
        float r0 = warp_sum(sum[q]);
        float r1 = warp_sum(a0[q]);
        float r2 = warp_sum(a1[q]);
        float r3 = warp_sum(a2[q]);
        float r4 = warp_sum(a3[q]);
        float r5 = warp_sum(as[q]);
        if (lane == 0) {
            atomicAdd(&s_red[q * 6 + 0], r0);
            atomicAdd(&s_red[q * 6 + 1], r1);
            atomicAdd(&s_red[q * 6 + 2], r2);
            atomicAdd(&s_red[q * 6 + 3], r3);
            atomicAdd(&s_red[q * 6 + 4], r4);
            atomicAdd(&s_red[q * 6 + 5], r5);
        }
    }
    __syncthreads();

    // ---- Epilogue: densities / colors / sizes; publish inv + log2(inv) ----
    if (tid < QPB) {
        int q = tid;
        float inv = 1.f / (s_red[q * 6 + 0] + 1e-8f);
        s_inv[q] = inv;
        s_L[q] = __log2f(inv);
        float f0 = s_red[q * 6 + 1] * inv;
        float f1 = s_red[q * 6 + 2] * inv;
        float f2 = s_red[q * 6 + 3] * inv;
        float f3 = s_red[q * 6 + 4] * inv;
        float sz = s_red[q * 6 + 5] * inv;
        int row = qbase + q;
        out[row] = fmaxf(f0, 0.f) + log1pf(__expf(-fabsf(f0)));  // softplus
        float* oc = out + NQ + (size_t)row * 3;
        oc[0] = 1.f / (1.f + __expf(-f1));
        oc[1] = 1.f / (1.f + __expf(-f2));
        oc[2] = 1.f / (1.f + __expf(-f3));
        out[4 * NQ + row] = sz;
    }
    __syncthreads();

    float inv_r[QPB], L_r[QPB];
    #pragma unroll
    for (int q = 0; q < QPB; q++) { inv_r[q] = s_inv[q]; L_r[q] = s_L[q]; }

    float* wout = out + (size_t)5 * NQ + (size_t)qbase * NV;

    // ---- Phase 2a: cached voxels — scale + store ----
    #pragma unroll 2
    for (int v = tid; v < VCACHE; v += THREADS) {
        #pragma unroll
        for (int q = 0; q < QPB; q++) {
            float w = s_wc[q * VCACHE + v] * inv_r[q];
            st_stream_f(wout + (size_t)q * NV + v, w);
        }
    }

    // ---- Phase 2b: remaining voxels — recompute normalized w directly ----
    #pragma unroll 2
    for (int v = VCACHE + tid; v < NV; v += THREADS) {
        float4 A = g_vox_a[v];
        #pragma unroll
        for (int q = 0; q < QPB; q++) {
            float d2 = q2[q] + A.w;
            d2 = fmaf(qx[q], A.x, d2);
            d2 = fmaf(qy[q], A.y, d2);
            d2 = fmaf(qz[q], A.z, d2);
            d2 = fmaxf(d2, 0.f);
            float d = fast_sqrt(d2);
            float wn = fast_ex2(fmaf(d, C, L_r[q]));  // exp(-d/2) * inv
            st_stream_f(wout + (size_t)q * NV + v, wn);
        }
    }
}

extern "C" void kernel_launch(void* const* d_in, const int* in_sizes, int n_in,
                              void* d_out, int out_size) {
    const float* qp = (const float*)d_in[0];  // query_points [NQ,3]
    const float* vc = (const float*)d_in[1];  // voxel_coords [NV,3]
    const float* vf = (const float*)d_in[2];  // voxel_features [NV,4]
    const float* vs = (const float*)d_in[3];  // voxel_sizes [NV]
    float* out = (float*)d_out;

    pack_voxels_kernel<<<(NV + 255) / 256, 256>>>(vc, vf, vs);

    cudaFuncSetAttribute(svg_main_kernel,
                         cudaFuncAttributeMaxDynamicSharedMemorySize,
                         SMEM_WC_BYTES);
    svg_main_kernel<<<NQ / QPB, THREADS, SMEM_WC_BYTES>>>(qp, out);
}

// round 4
// speedup vs baseline: 1.4490x; 1.1223x over previous
#include <cuda_runtime.h>
#include <cstddef>

// Problem constants (fixed by the reference setup_inputs)
#define NQ 16384
#define NV 8192
#define QPB 4            // query rows per CTA (register-resident)
#define THREADS 256

// Packed voxel data (scratch via __device__ globals; allocation-free)
__device__ float4 g_vox_a[NV];   // (-2*cx, -2*cy, -2*cz, cx^2+cy^2+cz^2)
__device__ float4 g_vox_f[NV];   // features
__device__ float  g_vox_s[NV];   // sizes

__device__ __forceinline__ float fast_sqrt(float x) {
    float r; asm("sqrt.approx.f32 %0, %1;" : "=f"(r) : "f"(x)); return r;
}
__device__ __forceinline__ float fast_ex2(float x) {
    float r; asm("ex2.approx.f32 %0, %1;" : "=f"(r) : "f"(x)); return r;
}
__device__ __forceinline__ float warp_sum(float v) {
    #pragma unroll
    for (int o = 16; o; o >>= 1) v += __shfl_xor_sync(0xffffffffu, v, o);
    return v;
}
__device__ __forceinline__ void st_stream_f(float* p, float v) {
    asm volatile("st.global.cs.f32 [%0], %1;" :: "l"(p), "f"(v) : "memory");
}

__global__ void pack_voxels_kernel(const float* __restrict__ vc,
                                   const float* __restrict__ vf,
                                   const float* __restrict__ vs) {
    int v = blockIdx.x * blockDim.x + threadIdx.x;
    if (v < NV) {
        float x = vc[3 * v + 0], y = vc[3 * v + 1], z = vc[3 * v + 2];
        g_vox_a[v] = make_float4(-2.f * x, -2.f * y, -2.f * z,
                                 x * x + y * y + z * z);
        g_vox_f[v] = make_float4(vf[4 * v + 0], vf[4 * v + 1],
                                 vf[4 * v + 2], vf[4 * v + 3]);
        g_vox_s[v] = vs[v];
    }
}

__global__ __launch_bounds__(THREADS, 4)
void svg_main_kernel(const float* __restrict__ qp, float* __restrict__ out) {
    __shared__ float s_red[QPB * 6];       // per q: sum, f0..f3, size
    __shared__ float s_L[QPB];             // log2(1/(sum+eps))

    const int tid   = threadIdx.x;
    const int lane  = tid & 31;
    const int qbase = blockIdx.x * QPB;

    if (tid < QPB * 6) s_red[tid] = 0.f;

    float qx[QPB], qy[QPB], qz[QPB], q2[QPB];
    #pragma unroll
    for (int q = 0; q < QPB; q++) {
        const float* p = qp + (size_t)(qbase + q) * 3;
        float x = __ldg(p + 0), y = __ldg(p + 1), z = __ldg(p + 2);
        qx[q] = x; qy[q] = y; qz[q] = z;
        q2[q] = x * x + y * y + z * z;
    }

    float sum[QPB], a0[QPB], a1[QPB], a2[QPB], a3[QPB], as[QPB];
    #pragma unroll
    for (int q = 0; q < QPB; q++) {
        sum[q] = 0.f; a0[q] = 0.f; a1[q] = 0.f;
        a2[q] = 0.f; a3[q] = 0.f; as[q] = 0.f;
    }

    __syncthreads();   // s_red zero visible before post-loop atomics

    const float C = -0.72134752044f;  // -0.5 * log2(e)

    // ---- Phase 1: accumulate row sums and feature/size accumulators ----
    #pragma unroll 4
    for (int v = tid; v < NV; v += THREADS) {
        float4 A = g_vox_a[v];
        float4 F = g_vox_f[v];
        float  S = g_vox_s[v];
        #pragma unroll
        for (int q = 0; q < QPB; q++) {
            float d2 = q2[q] + A.w;
            d2 = fmaf(qx[q], A.x, d2);
            d2 = fmaf(qy[q], A.y, d2);
            d2 = fmaf(qz[q], A.z, d2);
            d2 = fmaxf(d2, 0.f);
            float d = fast_sqrt(d2);
            float w = fast_ex2(d * C);           // exp(-d/2)
            sum[q] += w;
            a0[q] = fmaf(w, F.x, a0[q]);
            a1[q] = fmaf(w, F.y, a1[q]);
            a2[q] = fmaf(w, F.z, a2[q]);
            a3[q] = fmaf(w, F.w, a3[q]);
            as[q] = fmaf(w, S,   as[q]);
        }
    }

    // ---- Block reduction: warp shuffle, then one smem atomic per warp ----
    #pragma unroll
    for (int q = 0; q < QPB; q++) {
        float r0 = warp_sum(sum[q]);
        float r1 = warp_sum(a0[q]);
        float r2 = warp_sum(a1[q]);
        float r3 = warp_sum(a2[q]);
        float r4 = warp_sum(a3[q]);
        float r5 = warp_sum(as[q]);
        if (lane == 0) {
            atomicAdd(&s_red[q * 6 + 0], r0);
            atomicAdd(&s_red[q * 6 + 1], r1);
            atomicAdd(&s_red[q * 6 + 2], r2);
            atomicAdd(&s_red[q * 6 + 3], r3);
            atomicAdd(&s_red[q * 6 + 4], r4);
            atomicAdd(&s_red[q * 6 + 5], r5);
        }
    }
    __syncthreads();

    // ---- Epilogue: densities / colors / sizes; publish log2(inv) ----
    if (tid < QPB) {
        int q = tid;
        float inv = 1.f / (s_red[q * 6 + 0] + 1e-8f);
        s_L[q] = __log2f(inv);
        float f0 = s_red[q * 6 + 1] * inv;
        float f1 = s_red[q * 6 + 2] * inv;
        float f2 = s_red[q * 6 + 3] * inv;
        float f3 = s_red[q * 6 + 4] * inv;
        float sz = s_red[q * 6 + 5] * inv;
        int row = qbase + q;
        out[row] = fmaxf(f0, 0.f) + log1pf(__expf(-fabsf(f0)));  // softplus
        float* oc = out + NQ + (size_t)row * 3;
        oc[0] = 1.f / (1.f + __expf(-f1));
        oc[1] = 1.f / (1.f + __expf(-f2));
        oc[2] = 1.f / (1.f + __expf(-f3));
        out[4 * NQ + row] = sz;
    }
    __syncthreads();

    float L_r[QPB];
    #pragma unroll
    for (int q = 0; q < QPB; q++) L_r[q] = s_L[q];

    float* wout = out + (size_t)5 * NQ + (size_t)qbase * NV;

    // ---- Phase 2: recompute normalized w and stream to gmem ----
    #pragma unroll 4
    for (int v = tid; v < NV; v += THREADS) {
        float4 A = g_vox_a[v];
        #pragma unroll
        for (int q = 0; q < QPB; q++) {
            float d2 = q2[q] + A.w;
            d2 = fmaf(qx[q], A.x, d2);
            d2 = fmaf(qy[q], A.y, d2);
            d2 = fmaf(qz[q], A.z, d2);
            d2 = fmaxf(d2, 0.f);
            float d = fast_sqrt(d2);
            float wn = fast_ex2(fmaf(d, C, L_r[q]));  // exp(-d/2) * inv
            st_stream_f(wout + (size_t)q * NV + v, wn);
        }
    }
}

extern "C" void kernel_launch(void* const* d_in, const int* in_sizes, int n_in,
                              void* d_out, int out_size) {
    const float* qp = (const float*)d_in[0];  // query_points [NQ,3]
    const float* vc = (const float*)d_in[1];  // voxel_coords [NV,3]
    const float* vf = (const float*)d_in[2];  // voxel_features [NV,4]
    const float* vs = (const float*)d_in[3];  // voxel_sizes [NV]
    float* out = (float*)d_out;

    pack_voxels_kernel<<<(NV + 255) / 256, 256>>>(vc, vf, vs);

    svg_main_kernel<<<NQ / QPB, THREADS>>>(qp, out);
}

// round 5
// speedup vs baseline: 1.7314x; 1.1949x over previous
#include <cuda_runtime.h>
#include <cuda_fp16.h>
#include <cstddef>

// Problem constants (fixed by the reference setup_inputs)
#define NQ 16384
#define NV 8192
#define QPB 4            // query rows per CTA (register-resident)
#define THREADS 256
#define SMEM_BYTES (QPB * NV * 2)   // 65536 bytes (fp16 weight staging)

// Packed voxel data (scratch via __device__ globals; allocation-free)
__device__ float4 g_vox_a[NV];   // (-2*cx, -2*cy, -2*cz, cx^2+cy^2+cz^2)
__device__ float4 g_vox_f[NV];   // features
__device__ float  g_vox_s[NV];   // sizes

__device__ __forceinline__ float fast_sqrt(float x) {
    float r; asm("sqrt.approx.f32 %0, %1;" : "=f"(r) : "f"(x)); return r;
}
__device__ __forceinline__ float fast_ex2(float x) {
    float r; asm("ex2.approx.f32 %0, %1;" : "=f"(r) : "f"(x)); return r;
}
__device__ __forceinline__ float warp_sum(float v) {
    #pragma unroll
    for (int o = 16; o; o >>= 1) v += __shfl_xor_sync(0xffffffffu, v, o);
    return v;
}
// 4 streaming stores to the same v of 4 consecutive weight rows:
// immediate offsets (q*NV*4 bytes) -> one address chain instead of four.
__device__ __forceinline__ void st4_rows(float* base, float w0, float w1,
                                         float w2, float w3) {
    asm volatile(
        "st.global.cs.f32 [%0],        %1;\n\t"
        "st.global.cs.f32 [%0+32768],  %2;\n\t"
        "st.global.cs.f32 [%0+65536],  %3;\n\t"
        "st.global.cs.f32 [%0+98304],  %4;"
        :: "l"(base), "f"(w0), "f"(w1), "f"(w2), "f"(w3) : "memory");
}

__global__ void pack_voxels_kernel(const float* __restrict__ vc,
                                   const float* __restrict__ vf,
                                   const float* __restrict__ vs) {
    int v = blockIdx.x * blockDim.x + threadIdx.x;
    if (v < NV) {
        float x = vc[3 * v + 0], y = vc[3 * v + 1], z = vc[3 * v + 2];
        g_vox_a[v] = make_float4(-2.f * x, -2.f * y, -2.f * z,
                                 x * x + y * y + z * z);
        g_vox_f[v] = make_float4(vf[4 * v + 0], vf[4 * v + 1],
                                 vf[4 * v + 2], vf[4 * v + 3]);
        g_vox_s[v] = vs[v];
    }
}

__global__ __launch_bounds__(THREADS, 3)
void svg_main_kernel(const float* __restrict__ qp, float* __restrict__ out) {
    // Dynamic smem: two half2 arrays of NV entries each.
    // s01[v] holds (w_q0, w_q1); s23[v] holds (w_q2, w_q3).
    extern __shared__ __half2 s_wc[];
    __half2* s01 = s_wc;
    __half2* s23 = s_wc + NV;

    __shared__ float s_red[QPB * 6];       // per q: sum, f0..f3, size
    __shared__ float s_inv[QPB];

    const int tid   = threadIdx.x;
    const int lane  = tid & 31;
    const int qbase = blockIdx.x * QPB;

    if (tid < QPB * 6) s_red[tid] = 0.f;

    float qx[QPB], qy[QPB], qz[QPB], q2[QPB];
    #pragma unroll
    for (int q = 0; q < QPB; q++) {
        const float* p = qp + (size_t)(qbase + q) * 3;
        float x = __ldg(p + 0), y = __ldg(p + 1), z = __ldg(p + 2);
        qx[q] = x; qy[q] = y; qz[q] = z;
        q2[q] = x * x + y * y + z * z;
    }

    float sum[QPB], a0[QPB], a1[QPB], a2[QPB], a3[QPB], as[QPB];
    #pragma unroll
    for (int q = 0; q < QPB; q++) {
        sum[q] = 0.f; a0[q] = 0.f; a1[q] = 0.f;
        a2[q] = 0.f; a3[q] = 0.f; as[q] = 0.f;
    }

    __syncthreads();   // s_red zero visible before post-loop atomics

    const float C = -0.72134752044f;  // -0.5 * log2(e)

    // ---- Phase 1: accumulate row sums + stage fp16 weights ----
    #pragma unroll 4
    for (int v = tid; v < NV; v += THREADS) {
        float4 A = g_vox_a[v];
        float4 F = g_vox_f[v];
        float  S = g_vox_s[v];
        float w[QPB];
        #pragma unroll
        for (int q = 0; q < QPB; q++) {
            float d2 = q2[q] + A.w;
            d2 = fmaf(qx[q], A.x, d2);
            d2 = fmaf(qy[q], A.y, d2);
            d2 = fmaf(qz[q], A.z, d2);
            d2 = fmaxf(d2, 0.f);
            float d = fast_sqrt(d2);
            w[q] = fast_ex2(d * C);           // exp(-d/2)
            sum[q] += w[q];
            a0[q] = fmaf(w[q], F.x, a0[q]);
            a1[q] = fmaf(w[q], F.y, a1[q]);
            a2[q] = fmaf(w[q], F.z, a2[q]);
            a3[q] = fmaf(w[q], F.w, a3[q]);
            as[q] = fmaf(w[q], S,   as[q]);
        }
        s01[v] = __floats2half2_rn(w[0], w[1]);
        s23[v] = __floats2half2_rn(w[2], w[3]);
    }

    // ---- Block reduction: warp shuffle, then one smem atomic per warp ----
    #pragma unroll
    for (int q = 0; q < QPB; q++) {
        float r0 = warp_sum(sum[q]);
        float r1 = warp_sum(a0[q]);
        float r2 = warp_sum(a1[q]);
        float r3 = warp_sum(a2[q]);
        float r4 = warp_sum(a3[q]);
        float r5 = warp_sum(as[q]);
        if (lane == 0) {
            atomicAdd(&s_red[q * 6 + 0], r0);
            atomicAdd(&s_red[q * 6 + 1], r1);
            atomicAdd(&s_red[q * 6 + 2], r2);
            atomicAdd(&s_red[q * 6 + 3], r3);
            atomicAdd(&s_red[q * 6 + 4], r4);
            atomicAdd(&s_red[q * 6 + 5], r5);
        }
    }
    __syncthreads();

    // ---- Epilogue: densities / colors / sizes; publish inv ----
    if (tid < QPB) {
        int q = tid;
        float inv = 1.f / (s_red[q * 6 + 0] + 1e-8f);
        s_inv[q] = inv;
        float f0 = s_red[q * 6 + 1] * inv;
        float f1 = s_red[q * 6 + 2] * inv;
        float f2 = s_red[q * 6 + 3] * inv;
        float f3 = s_red[q * 6 + 4] * inv;
        float sz = s_red[q * 6 + 5] * inv;
        int row = qbase + q;
        out[row] = fmaxf(f0, 0.f) + log1pf(__expf(-fabsf(f0)));  // softplus
        float* oc = out + NQ + (size_t)row * 3;
        oc[0] = 1.f / (1.f + __expf(-f1));
        oc[1] = 1.f / (1.f + __expf(-f2));
        oc[2] = 1.f / (1.f + __expf(-f3));
        out[4 * NQ + row] = sz;
    }
    __syncthreads();

    const float i0 = s_inv[0], i1 = s_inv[1], i2 = s_inv[2], i3 = s_inv[3];

    float* wout = out + (size_t)5 * NQ + (size_t)qbase * NV;

    // ---- Phase 2: unstage, scale in fp32, stream to gmem ----
    // Each thread reads the slots it wrote (no extra sync needed beyond the
    // reduction syncthreads above).
    #pragma unroll 4
    for (int v = tid; v < NV; v += THREADS) {
        float2 w01 = __half22float2(s01[v]);
        float2 w23 = __half22float2(s23[v]);
        st4_rows(wout + v, w01.x * i0, w01.y * i1, w23.x * i2, w23.y * i3);
    }
}

extern "C" void kernel_launch(void* const* d_in, const int* in_sizes, int n_in,
                              void* d_out, int out_size) {
    const float* qp = (const float*)d_in[0];  // query_points [NQ,3]
    const float* vc = (const float*)d_in[1];  // voxel_coords [NV,3]
    const float* vf = (const float*)d_in[2];  // voxel_features [NV,4]
    const float* vs = (const float*)d_in[3];  // voxel_sizes [NV]
    float* out = (float*)d_out;

    pack_voxels_kernel<<<(NV + 255) / 256, 256>>>(vc, vf, vs);

    cudaFuncSetAttribute(svg_main_kernel,
                         cudaFuncAttributeMaxDynamicSharedMemorySize,
                         SMEM_BYTES);
    svg_main_kernel<<<NQ / QPB, THREADS, SMEM_BYTES>>>(qp, out);
}